// round 1
// baseline (speedup 1.0000x reference)
#include <cuda_runtime.h>
#include <math.h>

// Problem constants
#define BB 8
#define CC 128
#define HS 62
#define WS 62
#define HH 64
#define WW 64
#define GG 4
#define PP 9

// Scratch (static device arrays; allocation-free per harness rules)
__device__ float g_x_nhwc[BB*HS*WS*CC];   // x transposed to NHWC
__device__ float g_y     [BB*HH*WW*CC];   // y = conv1x1(pad(x)) NHWC
__device__ float g_xproj [BB*HH*WW*CC];
__device__ float g_d     [BB*HH*WW*CC];   // dw+LN+GELU
__device__ float g_om    [BB*HH*WW*CC];   // cols 0..71 offsets, 72..107 mask logits
__device__ float g_mask  [BB*HH*WW*36];
__device__ float g_samp  [BB*HH*WW*CC];
__device__ float g_onh   [BB*HH*WW*CC];   // out_proj result NHWC
__device__ float g_wconvT[CC*CC];
__device__ float g_wcomb [CC*CC];
__device__ float g_bcomb [CC];

// ---------------------------------------------------------------------------
// prep: transpose conv_w (OIHW 1x1 -> [I][O]) and build combined offset/mask W
// ---------------------------------------------------------------------------
__global__ void prep_kernel(const float* __restrict__ conv_w,
                            const float* __restrict__ off_w,
                            const float* __restrict__ off_b,
                            const float* __restrict__ mask_w,
                            const float* __restrict__ mask_b) {
    int idx = blockIdx.x * blockDim.x + threadIdx.x;
    if (idx < CC*CC) {
        int o = idx / CC, i = idx % CC;
        g_wconvT[i*CC + o] = conv_w[idx];
        int k = o, n = i;  // reuse decomposition: row k, col n
        float v = 0.f;
        if (n < 72)       v = off_w[k*72 + n];
        else if (n < 108) v = mask_w[k*36 + (n-72)];
        g_wcomb[idx] = v;
        if (idx < CC) {
            g_bcomb[idx] = (idx < 72) ? off_b[idx]
                         : (idx < 108 ? mask_b[idx-72] : 0.f);
        }
    }
}

// ---------------------------------------------------------------------------
// NCHW (8,128,62,62) -> NHWC scratch
// ---------------------------------------------------------------------------
__global__ void transpose_in(const float* __restrict__ x) {
    __shared__ float tile[32][33];
    int b = blockIdx.z;
    int s0 = blockIdx.x * 32, c0 = blockIdx.y * 32;
    int tx = threadIdx.x, ty = threadIdx.y;
    const int S = HS*WS; // 3844
#pragma unroll
    for (int i = 0; i < 4; i++) {
        int ch = c0 + ty + i*8, s = s0 + tx;
        if (s < S) tile[ty+i*8][tx] = x[((size_t)(b*CC + ch))*S + s];
    }
    __syncthreads();
#pragma unroll
    for (int i = 0; i < 4; i++) {
        int s = s0 + ty + i*8, ch = c0 + tx;
        if (s < S) g_x_nhwc[((size_t)(b*S + s))*CC + ch] = tile[tx][ty+i*8];
    }
}

// ---------------------------------------------------------------------------
// Fill border ring of y (pad=1 on a 1x1 conv -> border = bias only)
// ---------------------------------------------------------------------------
__global__ void border_fill(const float* __restrict__ conv_b) {
    int idx = blockIdx.x * blockDim.x + threadIdx.x;
    if (idx >= BB*HH*WW*CC) return;
    int c = idx & 127;
    int pix = idx >> 7;
    int hw = pix & 4095;
    int h = hw >> 6, w = hw & 63;
    if (h == 0 || h == 63 || w == 0 || w == 63) g_y[idx] = conv_b[c];
}

// ---------------------------------------------------------------------------
// Generic [M x 128] @ [128 x 128] + bias GEMM, BM=64, 256 threads,
// 8x4 register micro-tile. mode==1 remaps output rows into y's 64x64 interior.
// ---------------------------------------------------------------------------
__global__ __launch_bounds__(256) void gemm128(const float* __restrict__ A,
                                               const float* __restrict__ W,
                                               const float* __restrict__ bias,
                                               float* __restrict__ Cmat,
                                               int M, int mode) {
    __shared__ float As[64][32];
    __shared__ float Ws[32][128];
    int tid = threadIdx.x;
    int row0 = blockIdx.x * 64;
    int ct = tid & 31;      // col group: cols [ct*4, ct*4+4)
    int rt = tid >> 5;      // row group: rows [rt*8, rt*8+8)
    float acc[8][4];
#pragma unroll
    for (int i = 0; i < 8; i++)
#pragma unroll
        for (int j = 0; j < 4; j++) acc[i][j] = 0.f;

    int ar = tid >> 2;           // 0..63
    int ak = (tid & 3) * 8;      // 0,8,16,24
    int arow = row0 + ar; if (arow >= M) arow = M - 1;
    const float* Abase = A + (size_t)arow * 128;
    int wr = tid >> 5;           // 0..7
    int wc = (tid & 31) * 4;

    for (int kc = 0; kc < 4; kc++) {
        float4 a0 = *(const float4*)(Abase + kc*32 + ak);
        float4 a1 = *(const float4*)(Abase + kc*32 + ak + 4);
        *(float4*)&As[ar][ak]     = a0;
        *(float4*)&As[ar][ak + 4] = a1;
#pragma unroll
        for (int t = 0; t < 4; t++) {
            int k = wr + t*8;
            *(float4*)&Ws[k][wc] = *(const float4*)(W + (size_t)(kc*32 + k)*128 + wc);
        }
        __syncthreads();
#pragma unroll
        for (int k = 0; k < 32; k++) {
            float4 wv = *(const float4*)&Ws[k][ct*4];
#pragma unroll
            for (int i = 0; i < 8; i++) {
                float a = As[rt*8 + i][k];
                acc[i][0] += a * wv.x;
                acc[i][1] += a * wv.y;
                acc[i][2] += a * wv.z;
                acc[i][3] += a * wv.w;
            }
        }
        __syncthreads();
    }
    float4 bv = *(const float4*)(bias + ct*4);
#pragma unroll
    for (int i = 0; i < 8; i++) {
        int row = row0 + rt*8 + i;
        if (row < M) {
            float* cr;
            if (mode == 1) {
                int b = row / 3844;
                int r = row - b * 3844;
                int hh = r / 62;
                int ww2 = r - hh * 62;
                cr = Cmat + ((size_t)(b*4096 + (hh+1)*64 + ww2 + 1))*128;
            } else {
                cr = Cmat + (size_t)row * 128;
            }
            float4 o;
            o.x = acc[i][0] + bv.x; o.y = acc[i][1] + bv.y;
            o.z = acc[i][2] + bv.z; o.w = acc[i][3] + bv.w;
            *(float4*)(cr + ct*4) = o;
        }
    }
}

// ---------------------------------------------------------------------------
// depthwise 3x3 + LayerNorm(C) + exact GELU. One block (128 thr) per pixel.
// ---------------------------------------------------------------------------
__global__ __launch_bounds__(128) void dw_ln_gelu(const float* __restrict__ dw_w,
                                                  const float* __restrict__ dw_b,
                                                  const float* __restrict__ ln_g,
                                                  const float* __restrict__ ln_b) {
    int pix = blockIdx.x;
    int b = pix >> 12;
    int hw = pix & 4095;
    int h = hw >> 6, w = hw & 63;
    int c = threadIdx.x;
    float acc = dw_b[c];
#pragma unroll
    for (int kh = 0; kh < 3; kh++) {
        int hh = h + kh - 1;
        if ((unsigned)hh < 64u) {
#pragma unroll
            for (int kw = 0; kw < 3; kw++) {
                int ww2 = w + kw - 1;
                if ((unsigned)ww2 < 64u)
                    acc += g_y[((size_t)(b*4096 + hh*64 + ww2))*128 + c]
                         * dw_w[c*9 + kh*3 + kw];
            }
        }
    }
    float s = acc, s2 = acc * acc;
#pragma unroll
    for (int o = 16; o; o >>= 1) {
        s  += __shfl_xor_sync(0xffffffffu, s,  o);
        s2 += __shfl_xor_sync(0xffffffffu, s2, o);
    }
    __shared__ float rs[4], rs2[4];
    if ((c & 31) == 0) { rs[c >> 5] = s; rs2[c >> 5] = s2; }
    __syncthreads();
    float ts  = rs[0] + rs[1] + rs[2] + rs[3];
    float ts2 = rs2[0] + rs2[1] + rs2[2] + rs2[3];
    float mu  = ts * (1.f/128.f);
    float var = ts2 * (1.f/128.f) - mu*mu;
    float rstd = rsqrtf(var + 1e-5f);
    float v = (acc - mu) * rstd * ln_g[c] + ln_b[c];
    float gl = 0.5f * v * (1.f + erff(v * 0.70710678118654752440f));
    g_d[(size_t)pix*128 + c] = gl;
}

// ---------------------------------------------------------------------------
// softmax over P=9 per (pixel, group); one thread per (pixel, group)
// ---------------------------------------------------------------------------
__global__ void softmax9() {
    int idx = blockIdx.x * blockDim.x + threadIdx.x;
    if (idx >= BB*HH*WW*GG) return;
    int pix = idx >> 2;
    int g = idx & 3;
    const float* p = g_om + (size_t)pix*128 + 72 + g*9;
    float v[9];
    float mx = -1e30f;
#pragma unroll
    for (int i = 0; i < 9; i++) { v[i] = p[i]; mx = fmaxf(mx, v[i]); }
    float sum = 0.f;
#pragma unroll
    for (int i = 0; i < 9; i++) { v[i] = expf(v[i] - mx); sum += v[i]; }
    float inv = 1.f / sum;
    float* o = g_mask + (size_t)pix*36 + g*9;
#pragma unroll
    for (int i = 0; i < 9; i++) o[i] = v[i] * inv;
}

// ---------------------------------------------------------------------------
// DCNv3 core: bilinear gather + mask-weighted sum.
// One block per pixel, thread = (group, channel-in-group). Coordinates
// collapse to ix = w+1+dx[p]+off_x, iy = h+1+dy[p]+off_y in the padded frame;
// a corner contributes iff it maps to interior [1,64]^2.
// ---------------------------------------------------------------------------
__global__ __launch_bounds__(128) void dcn_core() {
    int pix = blockIdx.x;
    int b = pix >> 12;
    int hw = pix & 4095;
    int h = hw >> 6, w = hw & 63;
    int tid = threadIdx.x;
    __shared__ float soff[72];
    __shared__ float sm[36];
    if (tid < 72) soff[tid] = g_om[(size_t)pix*128 + tid];
    if (tid < 36) sm[tid]   = g_mask[(size_t)pix*36 + tid];
    __syncthreads();
    int g = tid >> 5, c = tid & 31;
    int ch = g*32 + c;
    const float* xp = g_xproj + (size_t)b * 4096 * 128;
    float acc = 0.f;
#pragma unroll
    for (int p = 0; p < 9; p++) {
        float ox = soff[(g*9 + p)*2];
        float oy = soff[(g*9 + p)*2 + 1];
        float mv = sm[g*9 + p];
        float ix = (float)(w + (p/3)) + ox;   // w + 1 + (p/3 - 1)
        float iy = (float)(h + (p%3)) + oy;   // h + 1 + (p%3 - 1)
        float x0f = floorf(ix), y0f = floorf(iy);
        int x0 = (int)x0f, y0 = (int)y0f;
        float fx = ix - x0f, fy = iy - y0f;
        bool xa = (x0 >= 1 && x0 <= 64);
        bool xb = (x0 >= 0 && x0 <= 63);  // x0+1 in [1,64]
        bool ya = (y0 >= 1 && y0 <= 64);
        bool yb = (y0 >= 0 && y0 <= 63);
        float v00 = 0.f, v10 = 0.f, v01 = 0.f, v11 = 0.f;
        if (ya) {
            const float* r = xp + ((size_t)((y0-1)*64))*128 + ch;
            if (xa) v00 = r[(size_t)(x0-1)*128];
            if (xb) v10 = r[(size_t)x0*128];
        }
        if (yb) {
            const float* r = xp + ((size_t)(y0*64))*128 + ch;
            if (xa) v01 = r[(size_t)(x0-1)*128];
            if (xb) v11 = r[(size_t)x0*128];
        }
        float top = v00 * (1.f - fx) + v10 * fx;
        float bot = v01 * (1.f - fx) + v11 * fx;
        acc += mv * (top * (1.f - fy) + bot * fy);
    }
    g_samp[(size_t)pix*128 + ch] = acc;
}

// ---------------------------------------------------------------------------
// NHWC scratch -> NCHW d_out
// ---------------------------------------------------------------------------
__global__ void transpose_out(float* __restrict__ out) {
    __shared__ float tile[32][33];
    int b = blockIdx.z;
    int s0 = blockIdx.x * 32, c0 = blockIdx.y * 32;
    int tx = threadIdx.x, ty = threadIdx.y;
#pragma unroll
    for (int i = 0; i < 4; i++) {
        int pixr = s0 + tx;       // wait: read coalesced in channel
        int chr = c0 + tx;
        int pr  = s0 + ty + i*8;
        tile[ty+i*8][tx] = g_onh[((size_t)(b*4096 + pr))*128 + chr];
        (void)pixr;
    }
    __syncthreads();
#pragma unroll
    for (int i = 0; i < 4; i++) {
        int chw = c0 + ty + i*8;
        int pixw = s0 + tx;
        out[((size_t)(b*128 + chw))*4096 + pixw] = tile[tx][ty+i*8];
    }
}

// ---------------------------------------------------------------------------
extern "C" void kernel_launch(void* const* d_in, const int* in_sizes, int n_in,
                              void* d_out, int out_size) {
    const float* x          = (const float*)d_in[0];
    const float* conv_w     = (const float*)d_in[1];
    const float* conv_b     = (const float*)d_in[2];
    const float* in_proj_w  = (const float*)d_in[3];
    const float* in_proj_b  = (const float*)d_in[4];
    const float* dw_w       = (const float*)d_in[5];
    const float* dw_b       = (const float*)d_in[6];
    const float* ln_g       = (const float*)d_in[7];
    const float* ln_b       = (const float*)d_in[8];
    const float* off_w      = (const float*)d_in[9];
    const float* off_b      = (const float*)d_in[10];
    const float* mask_w     = (const float*)d_in[11];
    const float* mask_b     = (const float*)d_in[12];
    const float* out_proj_w = (const float*)d_in[13];
    const float* out_proj_b = (const float*)d_in[14];
    float* out = (float*)d_out;

    float *xn, *y, *xp, *dbuf, *om, *samp, *onh, *wcT, *wcb, *bcb;
    cudaGetSymbolAddress((void**)&xn,   g_x_nhwc);
    cudaGetSymbolAddress((void**)&y,    g_y);
    cudaGetSymbolAddress((void**)&xp,   g_xproj);
    cudaGetSymbolAddress((void**)&dbuf, g_d);
    cudaGetSymbolAddress((void**)&om,   g_om);
    cudaGetSymbolAddress((void**)&samp, g_samp);
    cudaGetSymbolAddress((void**)&onh,  g_onh);
    cudaGetSymbolAddress((void**)&wcT,  g_wconvT);
    cudaGetSymbolAddress((void**)&wcb,  g_wcomb);
    cudaGetSymbolAddress((void**)&bcb,  g_bcomb);

    prep_kernel<<<64, 256>>>(conv_w, off_w, off_b, mask_w, mask_b);
    transpose_in<<<dim3(121, 4, 8), dim3(32, 8)>>>(x);
    border_fill<<<(BB*HH*WW*CC + 255)/256, 256>>>(conv_b);

    const int M1 = BB*HS*WS;   // 30752
    const int M2 = BB*HH*WW;   // 32768
    gemm128<<<(M1 + 63)/64, 256>>>(xn, wcT, conv_b, y, M1, 1);
    gemm128<<<M2/64, 256>>>(y, in_proj_w, in_proj_b, xp, M2, 0);
    dw_ln_gelu<<<M2, 128>>>(dw_w, dw_b, ln_g, ln_b);
    gemm128<<<M2/64, 256>>>(dbuf, wcb, bcb, om, M2, 0);
    softmax9<<<(M2*GG + 255)/256, 256>>>();
    dcn_core<<<M2, 128>>>();
    gemm128<<<M2/64, 256>>>(samp, out_proj_w, out_proj_b, onh, M2, 0);
    transpose_out<<<dim3(128, 4, 8), dim3(32, 8)>>>(out);
}

// round 3
// speedup vs baseline: 1.3686x; 1.3686x over previous
#include <cuda_runtime.h>
#include <math.h>
#include <cstdint>

// Problem constants
#define BB 8
#define CC 128
#define HS 62
#define WS 62
#define HH 64
#define WW 64
#define GG 4
#define PP 9

// ---------------------------------------------------------------------------
// Scratch (static device arrays; allocation-free per harness rules)
// ---------------------------------------------------------------------------
__device__ float g_x_nhwc[BB*HS*WS*CC];
__device__ float g_y     [BB*HH*WW*CC];
__device__ float g_xproj [BB*HH*WW*CC];
__device__ float g_d     [BB*HH*WW*CC];
__device__ float g_om    [BB*HH*WW*CC];
__device__ float g_mask  [BB*HH*WW*36];
__device__ float g_samp  [BB*HH*WW*CC];
__device__ float g_onh   [BB*HH*WW*CC];
__device__ float g_Bimg  [4*CC*CC];      // B[n][k] row-major, tf32-rounded
__device__ float g_bcomb [CC];

__device__ __forceinline__ uint32_t f2tf32(float f) {
    uint32_t u;
    asm("cvt.rna.tf32.f32 %0, %1;" : "=r"(u) : "f"(f));
    return u;
}

// ---------------------------------------------------------------------------
// prep: build 4 tf32 B[n][k] matrices + combined bias
//   m=0: conv    B[n][k] = conv_w[n*128+k]  (OIHW 1x1, o=n, i=k)
//   m=1: inproj  B[n][k] = in_proj_w[k*128+n]
//   m=2: comb    B[n][k] = off_w[k*72+n] | mask_w[k*36+(n-72)] | 0
//   m=3: outproj B[n][k] = out_proj_w[k*128+n]
// ---------------------------------------------------------------------------
__global__ void prep_kernel(const float* __restrict__ conv_w,
                            const float* __restrict__ in_proj_w,
                            const float* __restrict__ off_w,
                            const float* __restrict__ off_b,
                            const float* __restrict__ mask_w,
                            const float* __restrict__ mask_b,
                            const float* __restrict__ out_proj_w) {
    int idx = blockIdx.x * blockDim.x + threadIdx.x;
    if (idx >= 4 * CC * CC) return;
    int m = idx >> 14;
    int e = idx & 16383;
    int n = e >> 7, k = e & 127;
    float v = 0.f;
    if (m == 0)      v = conv_w[n * CC + k];
    else if (m == 1) v = in_proj_w[k * CC + n];
    else if (m == 2) {
        if (n < 72)       v = off_w[k * 72 + n];
        else if (n < 108) v = mask_w[k * 36 + (n - 72)];
    } else           v = out_proj_w[k * CC + n];
    ((uint32_t*)g_Bimg)[idx] = f2tf32(v);
    if (idx < CC)
        g_bcomb[idx] = (idx < 72) ? off_b[idx] : (idx < 108 ? mask_b[idx - 72] : 0.f);
}

// ---------------------------------------------------------------------------
// NCHW (8,128,62,62) -> NHWC scratch
// ---------------------------------------------------------------------------
__global__ void transpose_in(const float* __restrict__ x) {
    __shared__ float tile[32][33];
    int b = blockIdx.z;
    int s0 = blockIdx.x * 32, c0 = blockIdx.y * 32;
    int tx = threadIdx.x, ty = threadIdx.y;
    const int S = HS * WS;
#pragma unroll
    for (int i = 0; i < 4; i++) {
        int ch = c0 + ty + i * 8, s = s0 + tx;
        if (s < S) tile[ty + i * 8][tx] = x[((size_t)(b * CC + ch)) * S + s];
    }
    __syncthreads();
#pragma unroll
    for (int i = 0; i < 4; i++) {
        int s = s0 + ty + i * 8, ch = c0 + tx;
        if (s < S) g_x_nhwc[((size_t)(b * S + s)) * CC + ch] = tile[tx][ty + i * 8];
    }
}

// ---------------------------------------------------------------------------
// Fill border ring of y (pad=1 on 1x1 conv -> border = bias only)
// ---------------------------------------------------------------------------
__global__ void border_fill(const float* __restrict__ conv_b) {
    int idx = blockIdx.x * blockDim.x + threadIdx.x;
    if (idx >= BB * HH * WW * CC) return;
    int c = idx & 127;
    int pix = idx >> 7;
    int hw = pix & 4095;
    int h = hw >> 6, w = hw & 63;
    if (h == 0 || h == 63 || w == 0 || w == 63) g_y[idx] = conv_b[c];
}

// ---------------------------------------------------------------------------
// tf32 mma.sync GEMM: C[M x 128] = A[M x 128] @ B^T + bias
// CTA = 128x128 tile, 256 threads / 8 warps, warp tile 32x64.
// m16n8k8 tf32 fragments; smem stride 132 -> conflict-free frag loads.
// mode==1: remap output rows into y's 64x64 interior.
// ---------------------------------------------------------------------------
#define ASTRIDE 132
#define SMEM_A_OFF 0
#define SMEM_B_OFF (128 * ASTRIDE)
#define SMEM_BIAS_OFF (2 * 128 * ASTRIDE)
#define SMEM_TOTAL_B ((2 * 128 * ASTRIDE + 128) * 4)

__global__ __launch_bounds__(256) void mma_gemm(const float* __restrict__ A,
                                                const float* __restrict__ Bimg,
                                                const float* __restrict__ bias,
                                                float* __restrict__ Cmat,
                                                int M, int mode) {
    extern __shared__ float smem[];
    float* As = smem + SMEM_A_OFF;
    float* Bs = smem + SMEM_B_OFF;
    float* sbias = smem + SMEM_BIAS_OFF;
    int tid = threadIdx.x;
    int lane = tid & 31;
    int wid = tid >> 5;
    int row0 = blockIdx.x * 128;

    if (tid < 128) sbias[tid] = bias[tid];

    // B: pre-rounded [n][k] row-major -> smem (bit copy)
#pragma unroll
    for (int j = 0; j < 16; j++) {
        int idx = tid + j * 256;          // float4 index
        int n = idx >> 5, k4 = (idx & 31) * 4;
        float4 v = *(const float4*)(Bimg + idx * 4);
        *(float4*)(Bs + n * ASTRIDE + k4) = v;
    }
    // A: coalesced load + tf32 round
#pragma unroll
    for (int j = 0; j < 16; j++) {
        int idx = tid + j * 256;
        int r = idx >> 5, k4 = (idx & 31) * 4;
        int grow = row0 + r; if (grow >= M) grow = M - 1;
        float4 v = *(const float4*)(A + (size_t)grow * 128 + k4);
        uint4 u;
        u.x = f2tf32(v.x); u.y = f2tf32(v.y); u.z = f2tf32(v.z); u.w = f2tf32(v.w);
        *(uint4*)(As + r * ASTRIDE + k4) = u;
    }
    __syncthreads();

    int wr = wid >> 1;     // row group 0..3 -> rows wr*32
    int wc = wid & 1;      // col half  0..1 -> cols wc*64
    float acc[2][8][4];
#pragma unroll
    for (int i = 0; i < 2; i++)
#pragma unroll
        for (int j = 0; j < 8; j++)
#pragma unroll
            for (int q = 0; q < 4; q++) acc[i][j][q] = 0.f;

    int lg = lane >> 2;    // 0..7
    int lk = lane & 3;     // 0..3

#pragma unroll
    for (int ks = 0; ks < 16; ks++) {
        int k0 = ks * 8;
        uint32_t a[2][4];
#pragma unroll
        for (int rg = 0; rg < 2; rg++) {
            const float* ab = As + (wr * 32 + rg * 16 + lg) * ASTRIDE + k0 + lk;
            a[rg][0] = __float_as_uint(ab[0]);
            a[rg][1] = __float_as_uint(ab[8 * ASTRIDE]);
            a[rg][2] = __float_as_uint(ab[4]);
            a[rg][3] = __float_as_uint(ab[8 * ASTRIDE + 4]);
        }
        uint32_t b[8][2];
#pragma unroll
        for (int nf = 0; nf < 8; nf++) {
            const float* bb = Bs + (wc * 64 + nf * 8 + lg) * ASTRIDE + k0 + lk;
            b[nf][0] = __float_as_uint(bb[0]);
            b[nf][1] = __float_as_uint(bb[4]);
        }
#pragma unroll
        for (int rg = 0; rg < 2; rg++)
#pragma unroll
            for (int nf = 0; nf < 8; nf++) {
                asm volatile(
                    "mma.sync.aligned.m16n8k8.row.col.f32.tf32.tf32.f32 "
                    "{%0,%1,%2,%3}, {%4,%5,%6,%7}, {%8,%9}, {%0,%1,%2,%3};"
                    : "+f"(acc[rg][nf][0]), "+f"(acc[rg][nf][1]),
                      "+f"(acc[rg][nf][2]), "+f"(acc[rg][nf][3])
                    : "r"(a[rg][0]), "r"(a[rg][1]), "r"(a[rg][2]), "r"(a[rg][3]),
                      "r"(b[nf][0]), "r"(b[nf][1]));
            }
    }

    // Epilogue: c0,c1 at (row=lg, col=2*lk..+1); c2,c3 at row+8
#pragma unroll
    for (int rg = 0; rg < 2; rg++) {
#pragma unroll
        for (int half = 0; half < 2; half++) {
            int row = row0 + wr * 32 + rg * 16 + lg + half * 8;
            if (row < M) {
                float* cr;
                if (mode == 1) {
                    int b2 = row / 3844;
                    int r = row - b2 * 3844;
                    int hh = r / 62;
                    int ww2 = r - hh * 62;
                    cr = Cmat + ((size_t)(b2 * 4096 + (hh + 1) * 64 + ww2 + 1)) * 128;
                } else {
                    cr = Cmat + (size_t)row * 128;
                }
#pragma unroll
                for (int nf = 0; nf < 8; nf++) {
                    int col = wc * 64 + nf * 8 + 2 * lk;
                    float2 o;
                    o.x = acc[rg][nf][half * 2 + 0] + sbias[col];
                    o.y = acc[rg][nf][half * 2 + 1] + sbias[col + 1];
                    *(float2*)(cr + col) = o;
                }
            }
        }
    }
}

// ---------------------------------------------------------------------------
// depthwise 3x3 + LayerNorm(C) + exact GELU. One block (128 thr) per pixel.
// ---------------------------------------------------------------------------
__global__ __launch_bounds__(128) void dw_ln_gelu(const float* __restrict__ dw_w,
                                                  const float* __restrict__ dw_b,
                                                  const float* __restrict__ ln_g,
                                                  const float* __restrict__ ln_b) {
    int pix = blockIdx.x;
    int b = pix >> 12;
    int hw = pix & 4095;
    int h = hw >> 6, w = hw & 63;
    int c = threadIdx.x;
    float acc = dw_b[c];
#pragma unroll
    for (int kh = 0; kh < 3; kh++) {
        int hh = h + kh - 1;
        if ((unsigned)hh < 64u) {
#pragma unroll
            for (int kw = 0; kw < 3; kw++) {
                int ww2 = w + kw - 1;
                if ((unsigned)ww2 < 64u)
                    acc += g_y[((size_t)(b * 4096 + hh * 64 + ww2)) * 128 + c]
                         * dw_w[c * 9 + kh * 3 + kw];
            }
        }
    }
    float s = acc, s2 = acc * acc;
#pragma unroll
    for (int o = 16; o; o >>= 1) {
        s  += __shfl_xor_sync(0xffffffffu, s,  o);
        s2 += __shfl_xor_sync(0xffffffffu, s2, o);
    }
    __shared__ float rs[4], rs2[4];
    if ((c & 31) == 0) { rs[c >> 5] = s; rs2[c >> 5] = s2; }
    __syncthreads();
    float ts  = rs[0] + rs[1] + rs[2] + rs[3];
    float ts2 = rs2[0] + rs2[1] + rs2[2] + rs2[3];
    float mu  = ts * (1.f / 128.f);
    float var = ts2 * (1.f / 128.f) - mu * mu;
    float rstd = rsqrtf(var + 1e-5f);
    float v = (acc - mu) * rstd * ln_g[c] + ln_b[c];
    float gl = 0.5f * v * (1.f + erff(v * 0.70710678118654752440f));
    g_d[(size_t)pix * 128 + c] = gl;
}

// ---------------------------------------------------------------------------
// softmax over P=9 per (pixel, group)
// ---------------------------------------------------------------------------
__global__ void softmax9() {
    int idx = blockIdx.x * blockDim.x + threadIdx.x;
    if (idx >= BB * HH * WW * GG) return;
    int pix = idx >> 2;
    int g = idx & 3;
    const float* p = g_om + (size_t)pix * 128 + 72 + g * 9;
    float v[9];
    float mx = -1e30f;
#pragma unroll
    for (int i = 0; i < 9; i++) { v[i] = p[i]; mx = fmaxf(mx, v[i]); }
    float sum = 0.f;
#pragma unroll
    for (int i = 0; i < 9; i++) { v[i] = expf(v[i] - mx); sum += v[i]; }
    float inv = 1.f / sum;
    float* o = g_mask + (size_t)pix * 36 + g * 9;
#pragma unroll
    for (int i = 0; i < 9; i++) o[i] = v[i] * inv;
}

// ---------------------------------------------------------------------------
// DCNv3 core: bilinear gather + mask-weighted sum.
// ---------------------------------------------------------------------------
__global__ __launch_bounds__(128) void dcn_core() {
    int pix = blockIdx.x;
    int b = pix >> 12;
    int hw = pix & 4095;
    int h = hw >> 6, w = hw & 63;
    int tid = threadIdx.x;
    __shared__ float soff[72];
    __shared__ float sm[36];
    if (tid < 72) soff[tid] = g_om[(size_t)pix * 128 + tid];
    if (tid < 36) sm[tid]   = g_mask[(size_t)pix * 36 + tid];
    __syncthreads();
    int g = tid >> 5, c = tid & 31;
    int ch = g * 32 + c;
    const float* xp = g_xproj + (size_t)b * 4096 * 128;
    float acc = 0.f;
#pragma unroll
    for (int p = 0; p < 9; p++) {
        float ox = soff[(g * 9 + p) * 2];
        float oy = soff[(g * 9 + p) * 2 + 1];
        float mv = sm[g * 9 + p];
        float ix = (float)(w + (p / 3)) + ox;
        float iy = (float)(h + (p % 3)) + oy;
        float x0f = floorf(ix), y0f = floorf(iy);
        int x0 = (int)x0f, y0 = (int)y0f;
        float fx = ix - x0f, fy = iy - y0f;
        bool xa = (x0 >= 1 && x0 <= 64);
        bool xb = (x0 >= 0 && x0 <= 63);
        bool ya = (y0 >= 1 && y0 <= 64);
        bool yb = (y0 >= 0 && y0 <= 63);
        float v00 = 0.f, v10 = 0.f, v01 = 0.f, v11 = 0.f;
        if (ya) {
            const float* r = xp + ((size_t)((y0 - 1) * 64)) * 128 + ch;
            if (xa) v00 = r[(size_t)(x0 - 1) * 128];
            if (xb) v10 = r[(size_t)x0 * 128];
        }
        if (yb) {
            const float* r = xp + ((size_t)(y0 * 64)) * 128 + ch;
            if (xa) v01 = r[(size_t)(x0 - 1) * 128];
            if (xb) v11 = r[(size_t)x0 * 128];
        }
        float top = v00 * (1.f - fx) + v10 * fx;
        float bot = v01 * (1.f - fx) + v11 * fx;
        acc += mv * (top * (1.f - fy) + bot * fy);
    }
    g_samp[(size_t)pix * 128 + ch] = acc;
}

// ---------------------------------------------------------------------------
// NHWC scratch -> NCHW d_out
// ---------------------------------------------------------------------------
__global__ void transpose_out(float* __restrict__ out) {
    __shared__ float tile[32][33];
    int b = blockIdx.z;
    int s0 = blockIdx.x * 32, c0 = blockIdx.y * 32;
    int tx = threadIdx.x, ty = threadIdx.y;
#pragma unroll
    for (int i = 0; i < 4; i++) {
        int chr = c0 + tx;
        int pr  = s0 + ty + i * 8;
        tile[ty + i * 8][tx] = g_onh[((size_t)(b * 4096 + pr)) * 128 + chr];
    }
    __syncthreads();
#pragma unroll
    for (int i = 0; i < 4; i++) {
        int chw = c0 + ty + i * 8;
        int pixw = s0 + tx;
        out[((size_t)(b * 128 + chw)) * 4096 + pixw] = tile[tx][ty + i * 8];
    }
}

// ---------------------------------------------------------------------------
extern "C" void kernel_launch(void* const* d_in, const int* in_sizes, int n_in,
                              void* d_out, int out_size) {
    const float* x          = (const float*)d_in[0];
    const float* conv_w     = (const float*)d_in[1];
    const float* conv_b     = (const float*)d_in[2];
    const float* in_proj_w  = (const float*)d_in[3];
    const float* in_proj_b  = (const float*)d_in[4];
    const float* dw_w       = (const float*)d_in[5];
    const float* dw_b       = (const float*)d_in[6];
    const float* ln_g       = (const float*)d_in[7];
    const float* ln_b       = (const float*)d_in[8];
    const float* off_w      = (const float*)d_in[9];
    const float* off_b      = (const float*)d_in[10];
    const float* mask_w     = (const float*)d_in[11];
    const float* mask_b     = (const float*)d_in[12];
    const float* out_proj_w = (const float*)d_in[13];
    const float* out_proj_b = (const float*)d_in[14];
    float* out = (float*)d_out;

    float *xn, *y, *xp, *dbuf, *om, *samp, *onh, *bimg, *bcb;
    cudaGetSymbolAddress((void**)&xn,   g_x_nhwc);
    cudaGetSymbolAddress((void**)&y,    g_y);
    cudaGetSymbolAddress((void**)&xp,   g_xproj);
    cudaGetSymbolAddress((void**)&dbuf, g_d);
    cudaGetSymbolAddress((void**)&om,   g_om);
    cudaGetSymbolAddress((void**)&samp, g_samp);
    cudaGetSymbolAddress((void**)&onh,  g_onh);
    cudaGetSymbolAddress((void**)&bimg, g_Bimg);
    cudaGetSymbolAddress((void**)&bcb,  g_bcomb);

    cudaFuncSetAttribute(mma_gemm, cudaFuncAttributeMaxDynamicSharedMemorySize, SMEM_TOTAL_B);

    prep_kernel<<<256, 256>>>(conv_w, in_proj_w, off_w, off_b, mask_w, mask_b, out_proj_w);
    transpose_in<<<dim3(121, 4, 8), dim3(32, 8)>>>(x);
    border_fill<<<(BB*HH*WW*CC + 255)/256, 256>>>(conv_b);

    const int M1 = BB*HS*WS;   // 30752
    const int M2 = BB*HH*WW;   // 32768
    mma_gemm<<<(M1 + 127)/128, 256, SMEM_TOTAL_B>>>(xn,   bimg,           conv_b,     y,    M1, 1);
    mma_gemm<<<M2/128,        256, SMEM_TOTAL_B>>>(y,    bimg + 16384,   in_proj_b,  xp,   M2, 0);
    dw_ln_gelu<<<M2, 128>>>(dw_w, dw_b, ln_g, ln_b);
    mma_gemm<<<M2/128,        256, SMEM_TOTAL_B>>>(dbuf, bimg + 2*16384, bcb,        om,   M2, 0);
    softmax9<<<(M2*GG + 255)/256, 256>>>();
    dcn_core<<<M2, 128>>>();
    mma_gemm<<<M2/128,        256, SMEM_TOTAL_B>>>(samp, bimg + 3*16384, out_proj_b, onh,  M2, 0);
    transpose_out<<<dim3(128, 4, 8), dim3(32, 8)>>>(out);
}

// round 6
// speedup vs baseline: 1.4140x; 1.0332x over previous
#include <cuda_runtime.h>
#include <math.h>
#include <cstdint>

#define BB 8
#define CC 128
#define HS 62
#define WS 62
#define HH 64
#define WW 64
#define GG 4
#define PP 9

// ---------------------------------------------------------------------------
// Scratch
// ---------------------------------------------------------------------------
__device__ float g_y     [BB*HH*WW*CC];
__device__ float g_xproj [BB*HH*WW*CC];
__device__ float g_d     [BB*HH*WW*CC];
__device__ float g_om    [BB*HH*WW*CC];
__device__ float g_samp  [BB*HH*WW*CC];
__device__ float g_Bimg  [4*CC*CC];      // B[n][k] row-major, tf32-rounded
__device__ float g_bcomb [CC];

__device__ __forceinline__ uint32_t f2tf32(float f) {
    uint32_t u;
    asm("cvt.rna.tf32.f32 %0, %1;" : "=r"(u) : "f"(f));
    return u;
}

// ---------------------------------------------------------------------------
// prep: 4 tf32 B[n][k] matrices + combined bias
// ---------------------------------------------------------------------------
__global__ void prep_kernel(const float* __restrict__ conv_w,
                            const float* __restrict__ in_proj_w,
                            const float* __restrict__ off_w,
                            const float* __restrict__ off_b,
                            const float* __restrict__ mask_w,
                            const float* __restrict__ mask_b,
                            const float* __restrict__ out_proj_w) {
    int idx = blockIdx.x * blockDim.x + threadIdx.x;
    if (idx >= 4 * CC * CC) return;
    int m = idx >> 14;
    int e = idx & 16383;
    int n = e >> 7, k = e & 127;
    float v = 0.f;
    if (m == 0)      v = conv_w[n * CC + k];
    else if (m == 1) v = in_proj_w[k * CC + n];
    else if (m == 2) {
        if (n < 72)       v = off_w[k * 72 + n];
        else if (n < 108) v = mask_w[k * 36 + (n - 72)];
    } else           v = out_proj_w[k * CC + n];
    ((uint32_t*)g_Bimg)[idx] = f2tf32(v);
    if (idx < CC)
        g_bcomb[idx] = (idx < 72) ? off_b[idx] : (idx < 108 ? mask_b[idx - 72] : 0.f);
}

// ---------------------------------------------------------------------------
// Border ring of y = bias
// ---------------------------------------------------------------------------
__global__ void border_fill(const float* __restrict__ conv_b) {
    int idx = blockIdx.x * blockDim.x + threadIdx.x;
    if (idx >= BB * HH * WW * CC) return;
    int c = idx & 127;
    int pix = idx >> 7;
    int hw = pix & 4095;
    int h = hw >> 6, w = hw & 63;
    if (h == 0 || h == 63 || w == 0 || w == 63) g_y[idx] = conv_b[c];
}

// ---------------------------------------------------------------------------
// Pipelined tf32 mma.sync GEMM: C[M x 128] = A[M x 128] @ B^T + bias
// CTA = 128x128 tile, 256 thr / 8 warps, warp tile 32x64.
// K split into 4 chunks of 32, A double-buffered (prefetch overlap).
// asrc: 0 = A is [M][128] row-major; 1 = A is NCHW x (transposing load)
// mode: 0 = NHWC direct; 1 = remap rows into y 64x64 interior; 2 = NCHW out
// smem floats: Bs[128*132] | As[2][128*36] | bias[128]  = 104,960 B
// ---------------------------------------------------------------------------
#define BSTR 132
#define ASTR 36
#define OFF_B 0
#define OFF_A0 (128*BSTR)
#define OFF_A1 (128*BSTR + 128*ASTR)
#define OFF_BIAS (128*BSTR + 2*128*ASTR)
#define SMEM_FLOATS (128*BSTR + 2*128*ASTR + 128)
#define SMEM_BYTES (SMEM_FLOATS * 4)

__global__ __launch_bounds__(256, 2) void mma_gemm(
        const float* __restrict__ A, const float* __restrict__ Bimg,
        const float* __restrict__ bias, float* __restrict__ Cmat,
        int M, int mode, int asrc) {
    extern __shared__ float smem[];
    float* Bs = smem + OFF_B;
    float* sbias = smem + OFF_BIAS;
    int tid = threadIdx.x;
    int lane = tid & 31;
    int wid = tid >> 5;
    int row0 = blockIdx.x * 128;

    if (tid < 128) sbias[tid] = bias[tid];

    // B full load (identity copy of pre-rounded [n][k])
#pragma unroll
    for (int j = 0; j < 16; j++) {
        int f4 = tid + j * 256;
        int n = f4 >> 5, k4 = (f4 & 31) * 4;
        *(float4*)(Bs + n * BSTR + k4) = *(const float4*)(Bimg + f4 * 4);
    }

    float rstage[16];
    // ---- prefetch chunk helper (inlined twice) ----
#define PREFETCH(kc) do {                                                     \
    int k0 = (kc) * 32;                                                       \
    if (asrc == 0) {                                                          \
        _Pragma("unroll")                                                     \
        for (int j = 0; j < 4; j++) {                                         \
            int f4 = tid + j * 256;                                           \
            int r = f4 >> 3, kq = (f4 & 7) * 4;                               \
            int grow = row0 + r; if (grow >= M) grow = M - 1;                 \
            float4 v = *(const float4*)(A + (size_t)grow * 128 + k0 + kq);    \
            rstage[j*4+0] = v.x; rstage[j*4+1] = v.y;                         \
            rstage[j*4+2] = v.z; rstage[j*4+3] = v.w;                         \
        }                                                                     \
    } else {                                                                  \
        _Pragma("unroll")                                                     \
        for (int j = 0; j < 16; j++) {                                        \
            int idx = tid + j * 256;                                          \
            int r = idx & 127, cl = idx >> 7;                                 \
            int grow = row0 + r; if (grow >= M) grow = M - 1;                 \
            int b = grow / 3844;                                              \
            int s = grow - b * 3844;                                          \
            rstage[j] = A[(size_t)(b * 128 + k0 + cl) * 3844 + s];            \
        }                                                                     \
    }                                                                         \
} while (0)

#define STORE_CHUNK(buf) do {                                                 \
    float* As = smem + ((buf) ? OFF_A1 : OFF_A0);                             \
    if (asrc == 0) {                                                          \
        _Pragma("unroll")                                                     \
        for (int j = 0; j < 4; j++) {                                         \
            int f4 = tid + j * 256;                                           \
            int r = f4 >> 3, kq = (f4 & 7) * 4;                               \
            uint4 u;                                                          \
            u.x = f2tf32(rstage[j*4+0]); u.y = f2tf32(rstage[j*4+1]);         \
            u.z = f2tf32(rstage[j*4+2]); u.w = f2tf32(rstage[j*4+3]);         \
            *(uint4*)(As + r * ASTR + kq) = u;                                \
        }                                                                     \
    } else {                                                                  \
        _Pragma("unroll")                                                     \
        for (int j = 0; j < 16; j++) {                                        \
            int idx = tid + j * 256;                                          \
            int r = idx & 127, cl = idx >> 7;                                 \
            ((uint32_t*)(As + r * ASTR + cl))[0] = f2tf32(rstage[j]);         \
        }                                                                     \
    }                                                                         \
} while (0)

    PREFETCH(0);
    STORE_CHUNK(0);
    __syncthreads();

    int wr = wid >> 1;
    int wc = wid & 1;
    float acc[2][8][4];
#pragma unroll
    for (int i = 0; i < 2; i++)
#pragma unroll
        for (int j = 0; j < 8; j++)
#pragma unroll
            for (int q = 0; q < 4; q++) acc[i][j][q] = 0.f;

    int lg = lane >> 2;
    int lk = lane & 3;

#pragma unroll
    for (int kc = 0; kc < 4; kc++) {
        if (kc < 3) PREFETCH(kc + 1);
        const float* As = smem + ((kc & 1) ? OFF_A1 : OFF_A0);
#pragma unroll
        for (int ks = 0; ks < 4; ks++) {
            int k0 = ks * 8;                 // within chunk
            int kg = kc * 32 + ks * 8;       // global k for B
            uint32_t a[2][4];
#pragma unroll
            for (int rg = 0; rg < 2; rg++) {
                const float* ab = As + (wr * 32 + rg * 16 + lg) * ASTR + k0 + lk;
                a[rg][0] = __float_as_uint(ab[0]);
                a[rg][1] = __float_as_uint(ab[8 * ASTR]);
                a[rg][2] = __float_as_uint(ab[4]);
                a[rg][3] = __float_as_uint(ab[8 * ASTR + 4]);
            }
            uint32_t b[8][2];
#pragma unroll
            for (int nf = 0; nf < 8; nf++) {
                const float* bb = Bs + (wc * 64 + nf * 8 + lg) * BSTR + kg + lk;
                b[nf][0] = __float_as_uint(bb[0]);
                b[nf][1] = __float_as_uint(bb[4]);
            }
#pragma unroll
            for (int rg = 0; rg < 2; rg++)
#pragma unroll
                for (int nf = 0; nf < 8; nf++) {
                    asm volatile(
                        "mma.sync.aligned.m16n8k8.row.col.f32.tf32.tf32.f32 "
                        "{%0,%1,%2,%3}, {%4,%5,%6,%7}, {%8,%9}, {%0,%1,%2,%3};"
                        : "+f"(acc[rg][nf][0]), "+f"(acc[rg][nf][1]),
                          "+f"(acc[rg][nf][2]), "+f"(acc[rg][nf][3])
                        : "r"(a[rg][0]), "r"(a[rg][1]), "r"(a[rg][2]), "r"(a[rg][3]),
                          "r"(b[nf][0]), "r"(b[nf][1]));
                }
        }
        if (kc < 3) {
            STORE_CHUNK((kc + 1) & 1);
            __syncthreads();
        }
    }

    // ------------------------ epilogue ------------------------
    if (mode == 2) {
        // stage into Bs region (free now), then coalesced NCHW writes
        __syncthreads();
        float* Cs = Bs;   // [col][row] stride BSTR
#pragma unroll
        for (int rg = 0; rg < 2; rg++)
#pragma unroll
            for (int half = 0; half < 2; half++) {
                int r = wr * 32 + rg * 16 + lg + half * 8;
#pragma unroll
                for (int nf = 0; nf < 8; nf++) {
                    int col = wc * 64 + nf * 8 + 2 * lk;
                    Cs[col * BSTR + r]       = acc[rg][nf][half * 2 + 0] + sbias[col];
                    Cs[(col + 1) * BSTR + r] = acc[rg][nf][half * 2 + 1] + sbias[col + 1];
                }
            }
        __syncthreads();
        int bimg2 = row0 >> 12;          // 4096 pixels per batch, 128 | 4096
        int pix0 = row0 & 4095;
#pragma unroll
        for (int j = 0; j < 16; j++) {
            int f4 = tid + j * 256;
            int ch = f4 >> 5, p4 = (f4 & 31) * 4;
            float4 v = *(const float4*)(Cs + ch * BSTR + p4);
            *(float4*)(Cmat + (size_t)(bimg2 * 128 + ch) * 4096 + pix0 + p4) = v;
        }
        return;
    }

#pragma unroll
    for (int rg = 0; rg < 2; rg++) {
#pragma unroll
        for (int half = 0; half < 2; half++) {
            int row = row0 + wr * 32 + rg * 16 + lg + half * 8;
            if (row < M) {
                float* cr;
                if (mode == 1) {
                    int b2 = row / 3844;
                    int r = row - b2 * 3844;
                    int hh = r / 62;
                    int ww2 = r - hh * 62;
                    cr = Cmat + ((size_t)(b2 * 4096 + (hh + 1) * 64 + ww2 + 1)) * 128;
                } else {
                    cr = Cmat + (size_t)row * 128;
                }
#pragma unroll
                for (int nf = 0; nf < 8; nf++) {
                    int col = wc * 64 + nf * 8 + 2 * lk;
                    float2 o;
                    o.x = acc[rg][nf][half * 2 + 0] + sbias[col];
                    o.y = acc[rg][nf][half * 2 + 1] + sbias[col + 1];
                    *(float2*)(cr + col) = o;
                }
            }
        }
    }
}

// ---------------------------------------------------------------------------
// depthwise 3x3 + LayerNorm(C) + exact GELU. One block (128 thr) per pixel.
// ---------------------------------------------------------------------------
__global__ __launch_bounds__(128) void dw_ln_gelu(const float* __restrict__ dw_w,
                                                  const float* __restrict__ dw_b,
                                                  const float* __restrict__ ln_g,
                                                  const float* __restrict__ ln_b) {
    int pix = blockIdx.x;
    int b = pix >> 12;
    int hw = pix & 4095;
    int h = hw >> 6, w = hw & 63;
    int c = threadIdx.x;
    float acc = dw_b[c];
#pragma unroll
    for (int kh = 0; kh < 3; kh++) {
        int hh = h + kh - 1;
        if ((unsigned)hh < 64u) {
#pragma unroll
            for (int kw = 0; kw < 3; kw++) {
                int ww2 = w + kw - 1;
                if ((unsigned)ww2 < 64u)
                    acc += g_y[((size_t)(b * 4096 + hh * 64 + ww2)) * 128 + c]
                         * dw_w[c * 9 + kh * 3 + kw];
            }
        }
    }
    float s = acc, s2 = acc * acc;
#pragma unroll
    for (int o = 16; o; o >>= 1) {
        s  += __shfl_xor_sync(0xffffffffu, s,  o);
        s2 += __shfl_xor_sync(0xffffffffu, s2, o);
    }
    __shared__ float rs[4], rs2[4];
    if ((c & 31) == 0) { rs[c >> 5] = s; rs2[c >> 5] = s2; }
    __syncthreads();
    float ts  = rs[0] + rs[1] + rs[2] + rs[3];
    float ts2 = rs2[0] + rs2[1] + rs2[2] + rs2[3];
    float mu  = ts * (1.f / 128.f);
    float var = ts2 * (1.f / 128.f) - mu * mu;
    float rstd = rsqrtf(var + 1e-5f);
    float v = (acc - mu) * rstd * ln_g[c] + ln_b[c];
    float gl = 0.5f * v * (1.f + erff(v * 0.70710678118654752440f));
    g_d[(size_t)pix * 128 + c] = gl;
}

// ---------------------------------------------------------------------------
// DCNv3 core with fused softmax: bilinear gather + mask-weighted sum.
// ---------------------------------------------------------------------------
__global__ __launch_bounds__(128) void dcn_core() {
    int pix = blockIdx.x;
    int b = pix >> 12;
    int hw = pix & 4095;
    int h = hw >> 6, w = hw & 63;
    int tid = threadIdx.x;
    __shared__ float som[108];   // 0..71 offsets, 72..107 mask logits->probs
    if (tid < 108) som[tid] = g_om[(size_t)pix * 128 + tid];
    __syncthreads();
    if (tid < 4) {
        float* p = som + 72 + tid * 9;
        float mx = -1e30f;
#pragma unroll
        for (int i = 0; i < 9; i++) mx = fmaxf(mx, p[i]);
        float sum = 0.f;
#pragma unroll
        for (int i = 0; i < 9; i++) { p[i] = expf(p[i] - mx); sum += p[i]; }
        float inv = 1.f / sum;
#pragma unroll
        for (int i = 0; i < 9; i++) p[i] *= inv;
    }
    __syncthreads();
    int g = tid >> 5, c = tid & 31;
    int ch = g * 32 + c;
    const float* xp = g_xproj + (size_t)b * 4096 * 128;
    float acc = 0.f;
#pragma unroll
    for (int p = 0; p < 9; p++) {
        float ox = som[(g * 9 + p) * 2];
        float oy = som[(g * 9 + p) * 2 + 1];
        float mv = som[72 + g * 9 + p];
        float ix = (float)(w + (p / 3)) + ox;
        float iy = (float)(h + (p % 3)) + oy;
        float x0f = floorf(ix), y0f = floorf(iy);
        int x0 = (int)x0f, y0 = (int)y0f;
        float fx = ix - x0f, fy = iy - y0f;
        bool xa = (x0 >= 1 && x0 <= 64);
        bool xb = (x0 >= 0 && x0 <= 63);
        bool ya = (y0 >= 1 && y0 <= 64);
        bool yb = (y0 >= 0 && y0 <= 63);
        float v00 = 0.f, v10 = 0.f, v01 = 0.f, v11 = 0.f;
        if (ya) {
            const float* r = xp + ((size_t)((y0 - 1) * 64)) * 128 + ch;
            if (xa) v00 = r[(size_t)(x0 - 1) * 128];
            if (xb) v10 = r[(size_t)x0 * 128];
        }
        if (yb) {
            const float* r = xp + ((size_t)(y0 * 64)) * 128 + ch;
            if (xa) v01 = r[(size_t)(x0 - 1) * 128];
            if (xb) v11 = r[(size_t)x0 * 128];
        }
        float top = v00 * (1.f - fx) + v10 * fx;
        float bot = v01 * (1.f - fx) + v11 * fx;
        acc += mv * (top * (1.f - fy) + bot * fy);
    }
    g_samp[(size_t)pix * 128 + ch] = acc;
}

// ---------------------------------------------------------------------------
extern "C" void kernel_launch(void* const* d_in, const int* in_sizes, int n_in,
                              void* d_out, int out_size) {
    const float* x          = (const float*)d_in[0];
    const float* conv_w     = (const float*)d_in[1];
    const float* conv_b     = (const float*)d_in[2];
    const float* in_proj_w  = (const float*)d_in[3];
    const float* in_proj_b  = (const float*)d_in[4];
    const float* dw_w       = (const float*)d_in[5];
    const float* dw_b       = (const float*)d_in[6];
    const float* ln_g       = (const float*)d_in[7];
    const float* ln_b       = (const float*)d_in[8];
    const float* off_w      = (const float*)d_in[9];
    const float* off_b      = (const float*)d_in[10];
    const float* mask_w     = (const float*)d_in[11];
    const float* mask_b     = (const float*)d_in[12];
    const float* out_proj_w = (const float*)d_in[13];
    const float* out_proj_b = (const float*)d_in[14];
    float* out = (float*)d_out;

    float *y, *xp, *dbuf, *om, *samp, *bimg, *bcb;
    cudaGetSymbolAddress((void**)&y,    g_y);
    cudaGetSymbolAddress((void**)&xp,   g_xproj);
    cudaGetSymbolAddress((void**)&dbuf, g_d);
    cudaGetSymbolAddress((void**)&om,   g_om);
    cudaGetSymbolAddress((void**)&samp, g_samp);
    cudaGetSymbolAddress((void**)&bimg, g_Bimg);
    cudaGetSymbolAddress((void**)&bcb,  g_bcomb);

    cudaFuncSetAttribute(mma_gemm, cudaFuncAttributeMaxDynamicSharedMemorySize, SMEM_BYTES);

    prep_kernel<<<256, 256>>>(conv_w, in_proj_w, off_w, off_b, mask_w, mask_b, out_proj_w);
    border_fill<<<(BB*HH*WW*CC + 255)/256, 256>>>(conv_b);

    const int M1 = BB*HS*WS;   // 30752
    const int M2 = BB*HH*WW;   // 32768
    mma_gemm<<<(M1 + 127)/128, 256, SMEM_BYTES>>>(x,    bimg,           conv_b,     y,   M1, 1, 1);
    mma_gemm<<<M2/128,        256, SMEM_BYTES>>>(y,    bimg + 16384,   in_proj_b,  xp,  M2, 0, 0);
    dw_ln_gelu<<<M2, 128>>>(dw_w, dw_b, ln_g, ln_b);
    mma_gemm<<<M2/128,        256, SMEM_BYTES>>>(dbuf, bimg + 2*16384, bcb,        om,  M2, 0, 0);
    dcn_core<<<M2, 128>>>();
    mma_gemm<<<M2/128,        256, SMEM_BYTES>>>(samp, bimg + 3*16384, out_proj_b, out, M2, 2, 0);
}

// round 8
// speedup vs baseline: 1.6741x; 1.1840x over previous
#include <cuda_runtime.h>
#include <math.h>
#include <cstdint>

#define BB 8
#define CC 128
#define HS 62
#define WS 62
#define HH 64
#define WW 64
#define GG 4
#define PP 9

// ---------------------------------------------------------------------------
// Scratch
// ---------------------------------------------------------------------------
__device__ float g_y     [BB*HH*WW*CC];
__device__ float g_xproj [BB*HH*WW*CC];
__device__ float g_d     [BB*HH*WW*CC];
__device__ float g_om    [BB*HH*WW*CC];
__device__ float g_samp  [BB*HH*WW*CC];
__device__ float g_Bimg  [4*CC*CC];      // B[n][k] row-major, tf32-rounded
__device__ float g_bcomb [CC];

__device__ __forceinline__ uint32_t f2tf32(float f) {
    uint32_t u;
    asm("cvt.rna.tf32.f32 %0, %1;" : "=r"(u) : "f"(f));
    return u;
}
__device__ __forceinline__ float f2tf32f(float f) {
    return __uint_as_float(f2tf32(f));
}
__device__ __forceinline__ uint32_t s2u(const void* p) {
    return (uint32_t)__cvta_generic_to_shared(p);
}
__device__ __forceinline__ void cp_async16(uint32_t dst, const void* src) {
    asm volatile("cp.async.cg.shared.global [%0], [%1], 16;" :: "r"(dst), "l"(src));
}
#define CP_COMMIT() asm volatile("cp.async.commit_group;" ::: "memory")
#define CP_WAIT(n)  asm volatile("cp.async.wait_group %0;" :: "n"(n) : "memory")

// ---------------------------------------------------------------------------
// prep: 4 tf32 B[n][k] matrices + combined bias
// ---------------------------------------------------------------------------
__global__ void prep_kernel(const float* __restrict__ conv_w,
                            const float* __restrict__ in_proj_w,
                            const float* __restrict__ off_w,
                            const float* __restrict__ off_b,
                            const float* __restrict__ mask_w,
                            const float* __restrict__ mask_b,
                            const float* __restrict__ out_proj_w) {
    int idx = blockIdx.x * blockDim.x + threadIdx.x;
    if (idx >= 4 * CC * CC) return;
    int m = idx >> 14;
    int e = idx & 16383;
    int n = e >> 7, k = e & 127;
    float v = 0.f;
    if (m == 0)      v = conv_w[n * CC + k];
    else if (m == 1) v = in_proj_w[k * CC + n];
    else if (m == 2) {
        if (n < 72)       v = off_w[k * 72 + n];
        else if (n < 108) v = mask_w[k * 36 + (n - 72)];
    } else           v = out_proj_w[k * CC + n];
    ((uint32_t*)g_Bimg)[idx] = f2tf32(v);
    if (idx < CC)
        g_bcomb[idx] = (idx < 72) ? off_b[idx] : (idx < 108 ? mask_b[idx - 72] : 0.f);
}

// ---------------------------------------------------------------------------
// Border ring of y = bias (tf32-rounded: y is A of a tf32 GEMM)
// ---------------------------------------------------------------------------
__global__ void border_fill(const float* __restrict__ conv_b) {
    int idx = blockIdx.x * blockDim.x + threadIdx.x;
    if (idx >= BB * HH * WW * CC) return;
    int c = idx & 127;
    int pix = idx >> 7;
    int hw = pix & 4095;
    int h = hw >> 6, w = hw & 63;
    if (h == 0 || h == 63 || w == 0 || w == 63) g_y[idx] = f2tf32f(conv_b[c]);
}

// ---------------------------------------------------------------------------
// Shared GEMM geometry
// ---------------------------------------------------------------------------
#define BSTR 132
#define ASTR 36
#define OFF_B 0
#define OFF_A0 (128*BSTR)
#define OFF_A1 (128*BSTR + 128*ASTR)
#define OFF_BIAS (128*BSTR + 2*128*ASTR)
#define SMEM_FLOATS (128*BSTR + 2*128*ASTR + 128)
#define SMEM_BYTES (SMEM_FLOATS * 4)

#define DECL_ACC                                                              \
    float acc[2][8][4];                                                       \
    _Pragma("unroll") for (int i = 0; i < 2; i++)                             \
    _Pragma("unroll") for (int j = 0; j < 8; j++)                             \
    _Pragma("unroll") for (int q = 0; q < 4; q++) acc[i][j][q] = 0.f;

#define COMPUTE_CHUNK(kc)                                                     \
do {                                                                          \
    const float* As = smem + (((kc) & 1) ? OFF_A1 : OFF_A0);                  \
    _Pragma("unroll")                                                         \
    for (int ks = 0; ks < 4; ks++) {                                          \
        int k0 = ks * 8;                                                      \
        int kg = (kc) * 32 + ks * 8;                                          \
        uint32_t a[2][4];                                                     \
        _Pragma("unroll")                                                     \
        for (int rg = 0; rg < 2; rg++) {                                      \
            const float* ab = As + (wr * 32 + rg * 16 + lg) * ASTR + k0 + lk; \
            a[rg][0] = __float_as_uint(ab[0]);                                \
            a[rg][1] = __float_as_uint(ab[8 * ASTR]);                         \
            a[rg][2] = __float_as_uint(ab[4]);                                \
            a[rg][3] = __float_as_uint(ab[8 * ASTR + 4]);                     \
        }                                                                     \
        uint32_t bfr[8][2];                                                   \
        _Pragma("unroll")                                                     \
        for (int nf = 0; nf < 8; nf++) {                                      \
            const float* bb = Bs + (wc * 64 + nf * 8 + lg) * BSTR + kg + lk;  \
            bfr[nf][0] = __float_as_uint(bb[0]);                              \
            bfr[nf][1] = __float_as_uint(bb[4]);                              \
        }                                                                     \
        _Pragma("unroll")                                                     \
        for (int rg = 0; rg < 2; rg++)                                        \
        _Pragma("unroll")                                                     \
        for (int nf = 0; nf < 8; nf++) {                                      \
            asm volatile(                                                     \
                "mma.sync.aligned.m16n8k8.row.col.f32.tf32.tf32.f32 "         \
                "{%0,%1,%2,%3}, {%4,%5,%6,%7}, {%8,%9}, {%0,%1,%2,%3};"       \
                : "+f"(acc[rg][nf][0]), "+f"(acc[rg][nf][1]),                 \
                  "+f"(acc[rg][nf][2]), "+f"(acc[rg][nf][3])                  \
                : "r"(a[rg][0]), "r"(a[rg][1]), "r"(a[rg][2]), "r"(a[rg][3]), \
                  "r"(bfr[nf][0]), "r"(bfr[nf][1]));                          \
        }                                                                     \
    }                                                                         \
} while (0)

// ---------------------------------------------------------------------------
// GEMM (async): C[M x 128] = A[M x 128] @ B^T + bias; A already tf32-rounded.
// cp.async pipeline: B + A0 | A1 in flight before first barrier.
// mode: 0 = NHWC row-major out; 2 = NCHW out (final output)
// ---------------------------------------------------------------------------
__global__ __launch_bounds__(256, 2) void mma_gemm_async(
        const float* __restrict__ A, const float* __restrict__ Bimg,
        const float* __restrict__ bias, float* __restrict__ Cmat,
        int M, int mode) {
    extern __shared__ float smem[];
    float* Bs = smem + OFF_B;
    float* sbias = smem + OFF_BIAS;
    int tid = threadIdx.x;
    int lane = tid & 31;
    int wid = tid >> 5;
    int row0 = blockIdx.x * 128;

    if (tid < 128) sbias[tid] = bias[tid];

#define ISSUE_A(ck, buf)                                                      \
do {                                                                          \
    float* As_ = smem + ((buf) ? OFF_A1 : OFF_A0);                            \
    int k0_ = (ck) * 32;                                                      \
    _Pragma("unroll")                                                         \
    for (int j = 0; j < 4; j++) {                                             \
        int f4 = tid + j * 256;                                               \
        int r = f4 >> 3, kq = (f4 & 7) * 4;                                   \
        cp_async16(s2u(As_ + r * ASTR + kq),                                  \
                   A + (size_t)(row0 + r) * 128 + k0_ + kq);                  \
    }                                                                         \
} while (0)

    // B (64KB) + A chunk0 -> group 0; A chunk1 -> group 1
#pragma unroll
    for (int j = 0; j < 16; j++) {
        int f4 = tid + j * 256;
        int n = f4 >> 5, k4 = (f4 & 31) * 4;
        cp_async16(s2u(Bs + n * BSTR + k4), Bimg + f4 * 4);
    }
    ISSUE_A(0, 0);
    CP_COMMIT();
    ISSUE_A(1, 1);
    CP_COMMIT();
    CP_WAIT(1);
    __syncthreads();

    int wr = wid >> 1;
    int wc = wid & 1;
    int lg = lane >> 2;
    int lk = lane & 3;
    DECL_ACC;

#pragma unroll
    for (int kc = 0; kc < 4; kc++) {
        COMPUTE_CHUNK(kc);
        if (kc < 3) {
            __syncthreads();             // readers done with buf kc&1
            if (kc < 2) {
                ISSUE_A(kc + 2, kc & 1);
                CP_COMMIT();
                CP_WAIT(1);              // chunk kc+1 resident
            } else {
                CP_WAIT(0);              // chunk 3 resident
            }
            __syncthreads();
        }
    }

    if (mode == 2) {
        __syncthreads();
        float* Cs = Bs;   // [col][row] stride BSTR (B dead now)
#pragma unroll
        for (int rg = 0; rg < 2; rg++)
#pragma unroll
            for (int half = 0; half < 2; half++) {
                int r = wr * 32 + rg * 16 + lg + half * 8;
#pragma unroll
                for (int nf = 0; nf < 8; nf++) {
                    int col = wc * 64 + nf * 8 + 2 * lk;
                    Cs[col * BSTR + r]       = acc[rg][nf][half * 2 + 0] + sbias[col];
                    Cs[(col + 1) * BSTR + r] = acc[rg][nf][half * 2 + 1] + sbias[col + 1];
                }
            }
        __syncthreads();
        int bimg2 = row0 >> 12;
        int pix0 = row0 & 4095;
#pragma unroll
        for (int j = 0; j < 16; j++) {
            int f4 = tid + j * 256;
            int ch = f4 >> 5, p4 = (f4 & 31) * 4;
            float4 v = *(const float4*)(Cs + ch * BSTR + p4);
            *(float4*)(Cmat + (size_t)(bimg2 * 128 + ch) * 4096 + pix0 + p4) = v;
        }
        return;
    }

#pragma unroll
    for (int rg = 0; rg < 2; rg++)
#pragma unroll
        for (int half = 0; half < 2; half++) {
            int row = row0 + wr * 32 + rg * 16 + lg + half * 8;
            float* cr = Cmat + (size_t)row * 128;
#pragma unroll
            for (int nf = 0; nf < 8; nf++) {
                int col = wc * 64 + nf * 8 + 2 * lk;
                float2 o;
                o.x = acc[rg][nf][half * 2 + 0] + sbias[col];
                o.y = acc[rg][nf][half * 2 + 1] + sbias[col + 1];
                *(float2*)(cr + col) = o;
            }
        }
#undef ISSUE_A
}

// ---------------------------------------------------------------------------
// GEMM1 (NCHW transposing A-load): y_interior = x @ conv_w^T + b, tf32-rounded
// ---------------------------------------------------------------------------
__global__ __launch_bounds__(256, 2) void mma_gemm_nchw(
        const float* __restrict__ A, const float* __restrict__ Bimg,
        const float* __restrict__ bias, float* __restrict__ Cmat, int M) {
    extern __shared__ float smem[];
    float* Bs = smem + OFF_B;
    float* sbias = smem + OFF_BIAS;
    int tid = threadIdx.x;
    int lane = tid & 31;
    int wid = tid >> 5;
    int row0 = blockIdx.x * 128;

    if (tid < 128) sbias[tid] = bias[tid];

    // B via cp.async
#pragma unroll
    for (int j = 0; j < 16; j++) {
        int f4 = tid + j * 256;
        int n = f4 >> 5, k4 = (f4 & 31) * 4;
        cp_async16(s2u(Bs + n * BSTR + k4), Bimg + f4 * 4);
    }
    CP_COMMIT();

    float rstage[16];
#define PREFETCH1(kc)                                                         \
do {                                                                          \
    int k0 = (kc) * 32;                                                       \
    _Pragma("unroll")                                                         \
    for (int j = 0; j < 16; j++) {                                            \
        int idx = tid + j * 256;                                              \
        int r = idx & 127, cl = idx >> 7;                                     \
        int grow = row0 + r; if (grow >= M) grow = M - 1;                     \
        int b = grow / 3844;                                                  \
        int s = grow - b * 3844;                                              \
        rstage[j] = A[(size_t)(b * 128 + k0 + cl) * 3844 + s];                \
    }                                                                         \
} while (0)
#define STORE1(buf)                                                           \
do {                                                                          \
    float* As_ = smem + ((buf) ? OFF_A1 : OFF_A0);                            \
    _Pragma("unroll")                                                         \
    for (int j = 0; j < 16; j++) {                                            \
        int idx = tid + j * 256;                                              \
        int r = idx & 127, cl = idx >> 7;                                     \
        ((uint32_t*)(As_ + r * ASTR + cl))[0] = f2tf32(rstage[j]);            \
    }                                                                         \
} while (0)

    PREFETCH1(0);
    STORE1(0);
    CP_WAIT(0);
    __syncthreads();

    int wr = wid >> 1;
    int wc = wid & 1;
    int lg = lane >> 2;
    int lk = lane & 3;
    DECL_ACC;

#pragma unroll
    for (int kc = 0; kc < 4; kc++) {
        if (kc < 3) PREFETCH1(kc + 1);
        COMPUTE_CHUNK(kc);
        if (kc < 3) {
            STORE1((kc + 1) & 1);
            __syncthreads();
        }
    }

    // epilogue: remap rows into y 64x64 interior, tf32-round (y is next A)
#pragma unroll
    for (int rg = 0; rg < 2; rg++)
#pragma unroll
        for (int half = 0; half < 2; half++) {
            int row = row0 + wr * 32 + rg * 16 + lg + half * 8;
            if (row < M) {
                int b2 = row / 3844;
                int r = row - b2 * 3844;
                int hh = r / 62;
                int ww2 = r - hh * 62;
                float* cr = Cmat + ((size_t)(b2 * 4096 + (hh + 1) * 64 + ww2 + 1)) * 128;
#pragma unroll
                for (int nf = 0; nf < 8; nf++) {
                    int col = wc * 64 + nf * 8 + 2 * lk;
                    float2 o;
                    o.x = f2tf32f(acc[rg][nf][half * 2 + 0] + sbias[col]);
                    o.y = f2tf32f(acc[rg][nf][half * 2 + 1] + sbias[col + 1]);
                    *(float2*)(cr + col) = o;
                }
            }
        }
#undef PREFETCH1
#undef STORE1
}

// ---------------------------------------------------------------------------
// depthwise 3x3 + LayerNorm(C) + exact GELU; output tf32-rounded (next A)
// ---------------------------------------------------------------------------
__global__ __launch_bounds__(128) void dw_ln_gelu(const float* __restrict__ dw_w,
                                                  const float* __restrict__ dw_b,
                                                  const float* __restrict__ ln_g,
                                                  const float* __restrict__ ln_b) {
    int pix = blockIdx.x;
    int b = pix >> 12;
    int hw = pix & 4095;
    int h = hw >> 6, w = hw & 63;
    int c = threadIdx.x;
    float acc = dw_b[c];
#pragma unroll
    for (int kh = 0; kh < 3; kh++) {
        int hh = h + kh - 1;
        if ((unsigned)hh < 64u) {
#pragma unroll
            for (int kw = 0; kw < 3; kw++) {
                int ww2 = w + kw - 1;
                if ((unsigned)ww2 < 64u)
                    acc += g_y[((size_t)(b * 4096 + hh * 64 + ww2)) * 128 + c]
                         * dw_w[c * 9 + kh * 3 + kw];
            }
        }
    }
    float s = acc, s2 = acc * acc;
#pragma unroll
    for (int o = 16; o; o >>= 1) {
        s  += __shfl_xor_sync(0xffffffffu, s,  o);
        s2 += __shfl_xor_sync(0xffffffffu, s2, o);
    }
    __shared__ float rs[4], rs2[4];
    if ((c & 31) == 0) { rs[c >> 5] = s; rs2[c >> 5] = s2; }
    __syncthreads();
    float ts  = rs[0] + rs[1] + rs[2] + rs[3];
    float ts2 = rs2[0] + rs2[1] + rs2[2] + rs2[3];
    float mu  = ts * (1.f / 128.f);
    float var = ts2 * (1.f / 128.f) - mu * mu;
    float rstd = rsqrtf(var + 1e-5f);
    float v = (acc - mu) * rstd * ln_g[c] + ln_b[c];
    float gl = 0.5f * v * (1.f + erff(v * 0.70710678118654752440f));
    g_d[(size_t)pix * 128 + c] = f2tf32f(gl);
}

// ---------------------------------------------------------------------------
// DCNv3 core, fused softmax + precomputed gather plan.
// Phase A (36 thr): per (g,p) compute 4 corner addrs + mask-premultiplied
// bilinear weights (0 for invalid corners, addr clamped to 0).
// Phase B (128 thr): 4 coalesced loads + 4 FMA per point.
// Output tf32-rounded (samp is next GEMM's A).
// ---------------------------------------------------------------------------
__global__ __launch_bounds__(128) void dcn_core() {
    int pix = blockIdx.x;
    int b = pix >> 12;
    int hw = pix & 4095;
    int h = hw >> 6, w = hw & 63;
    int tid = threadIdx.x;
    __shared__ float som[108];
    __shared__ int   sa[36][4];
    __shared__ float swt[36][4];
    if (tid < 108) som[tid] = g_om[(size_t)pix * 128 + tid];
    __syncthreads();
    if (tid < 4) {
        float* p = som + 72 + tid * 9;
        float mx = -1e30f;
#pragma unroll
        for (int i = 0; i < 9; i++) mx = fmaxf(mx, p[i]);
        float sum = 0.f;
#pragma unroll
        for (int i = 0; i < 9; i++) { p[i] = expf(p[i] - mx); sum += p[i]; }
        float inv = 1.f / sum;
#pragma unroll
        for (int i = 0; i < 9; i++) p[i] *= inv;
    }
    __syncthreads();
    if (tid < 36) {
        int p = tid % 9;
        float ox = som[tid * 2];
        float oy = som[tid * 2 + 1];
        float mv = som[72 + tid];
        float ix = (float)(w + (p / 3)) + ox;
        float iy = (float)(h + (p % 3)) + oy;
        float x0f = floorf(ix), y0f = floorf(iy);
        int x0 = (int)x0f, y0 = (int)y0f;
        float fx = ix - x0f, fy = iy - y0f;
        bool xa = (x0 >= 1 && x0 <= 64);
        bool xb = (x0 >= 0 && x0 <= 63);
        bool ya = (y0 >= 1 && y0 <= 64);
        bool yb = (y0 >= 0 && y0 <= 63);
        float wx0 = 1.f - fx, wy0 = 1.f - fy;
        bool v0 = xa && ya, v1 = xb && ya, v2 = xa && yb, v3 = xb && yb;
        swt[tid][0] = v0 ? mv * wx0 * wy0 : 0.f;
        swt[tid][1] = v1 ? mv * fx  * wy0 : 0.f;
        swt[tid][2] = v2 ? mv * wx0 * fy  : 0.f;
        swt[tid][3] = v3 ? mv * fx  * fy  : 0.f;
        sa[tid][0] = v0 ? ((y0 - 1) * 64 + (x0 - 1)) * 128 : 0;
        sa[tid][1] = v1 ? ((y0 - 1) * 64 + x0) * 128 : 0;
        sa[tid][2] = v2 ? (y0 * 64 + (x0 - 1)) * 128 : 0;
        sa[tid][3] = v3 ? (y0 * 64 + x0) * 128 : 0;
    }
    __syncthreads();
    int g = tid >> 5, c = tid & 31;
    int ch = g * 32 + c;
    const float* xpc = g_xproj + (size_t)b * 4096 * 128 + ch;
    float acc = 0.f;
#pragma unroll
    for (int p = 0; p < 9; p++) {
        int i = g * 9 + p;
        int4 a = *(const int4*)sa[i];
        float4 wv = *(const float4*)swt[i];
        acc += wv.x * xpc[a.x];
        acc += wv.y * xpc[a.y];
        acc += wv.z * xpc[a.z];
        acc += wv.w * xpc[a.w];
    }
    g_samp[(size_t)pix * 128 + ch] = f2tf32f(acc);
}

// ---------------------------------------------------------------------------
extern "C" void kernel_launch(void* const* d_in, const int* in_sizes, int n_in,
                              void* d_out, int out_size) {
    const float* x          = (const float*)d_in[0];
    const float* conv_w     = (const float*)d_in[1];
    const float* conv_b     = (const float*)d_in[2];
    const float* in_proj_w  = (const float*)d_in[3];
    const float* in_proj_b  = (const float*)d_in[4];
    const float* dw_w       = (const float*)d_in[5];
    const float* dw_b       = (const float*)d_in[6];
    const float* ln_g       = (const float*)d_in[7];
    const float* ln_b       = (const float*)d_in[8];
    const float* off_w      = (const float*)d_in[9];
    const float* off_b      = (const float*)d_in[10];
    const float* mask_w     = (const float*)d_in[11];
    const float* mask_b     = (const float*)d_in[12];
    const float* out_proj_w = (const float*)d_in[13];
    const float* out_proj_b = (const float*)d_in[14];
    float* out = (float*)d_out;

    float *y, *xp, *dbuf, *om, *samp, *bimg, *bcb;
    cudaGetSymbolAddress((void**)&y,    g_y);
    cudaGetSymbolAddress((void**)&xp,   g_xproj);
    cudaGetSymbolAddress((void**)&dbuf, g_d);
    cudaGetSymbolAddress((void**)&om,   g_om);
    cudaGetSymbolAddress((void**)&samp, g_samp);
    cudaGetSymbolAddress((void**)&bimg, g_Bimg);
    cudaGetSymbolAddress((void**)&bcb,  g_bcomb);

    cudaFuncSetAttribute(mma_gemm_async, cudaFuncAttributeMaxDynamicSharedMemorySize, SMEM_BYTES);
    cudaFuncSetAttribute(mma_gemm_nchw,  cudaFuncAttributeMaxDynamicSharedMemorySize, SMEM_BYTES);

    prep_kernel<<<256, 256>>>(conv_w, in_proj_w, off_w, off_b, mask_w, mask_b, out_proj_w);
    border_fill<<<(BB*HH*WW*CC + 255)/256, 256>>>(conv_b);

    const int M1 = BB*HS*WS;   // 30752
    const int M2 = BB*HH*WW;   // 32768
    mma_gemm_nchw<<<(M1 + 127)/128, 256, SMEM_BYTES>>>(x, bimg, conv_b, y, M1);
    mma_gemm_async<<<M2/128, 256, SMEM_BYTES>>>(y,    bimg + 16384,   in_proj_b,  xp,  M2, 0);
    dw_ln_gelu<<<M2, 128>>>(dw_w, dw_b, ln_g, ln_b);
    mma_gemm_async<<<M2/128, 256, SMEM_BYTES>>>(dbuf, bimg + 2*16384, bcb,        om,  M2, 0);
    dcn_core<<<M2, 128>>>();
    mma_gemm_async<<<M2/128, 256, SMEM_BYTES>>>(samp, bimg + 3*16384, out_proj_b, out, M2, 2);
}